// round 1
// baseline (speedup 1.0000x reference)
#include <cuda_runtime.h>
#include <math.h>

#define NTAG 36
#define SEQ  512
#define HID  512
#define EMB  512
#define G4   2048   // 4*HID

// ---------------- device scratch (no allocations allowed) ----------------
__device__ __align__(16) float g_embeds[SEQ * EMB];        // 1 MB
__device__ __align__(16) float g_P[SEQ * G4];              // 4 MB: Wih@x + bih + bhh
__device__ __align__(16) float g_h[2][HID];
__device__ __align__(16) float g_c[HID];
__device__ int g_tag_list[NTAG * SEQ];
__device__ int g_tag_cnt[NTAG];
__device__ unsigned g_bar;

__device__ __forceinline__ float sigmoidf_(float x) {
    return 1.0f / (1.0f + __expf(-x));
}

// ---------------- init: reset barrier/counters, load h0/c0 ----------------
__global__ void k_init(const float* __restrict__ h0, const float* __restrict__ c0) {
    int j = threadIdx.x;            // 512 threads
    g_h[0][j] = h0[j];
    g_c[j]    = c0[j];
    if (j < NTAG) g_tag_cnt[j] = 0;
    if (j == 0)   g_bar = 0;
}

// ---------------- group timesteps by tag ----------------
__global__ void k_group(const int* __restrict__ tags) {
    int t = threadIdx.x;            // 512 threads
    int tag = tags[t];
    int pos = atomicAdd(&g_tag_cnt[tag], 1);
    g_tag_list[tag * SEQ + pos] = t;
}

// ---------------- embedding gather ----------------
__global__ void k_embed(const int* __restrict__ x, const float* __restrict__ emb) {
    int t = blockIdx.x;             // grid 512, block 128
    int row = x[t];
    const float4* src = (const float4*)emb + (size_t)row * (EMB / 4);
    float4* dst = (float4*)g_embeds + (size_t)t * (EMB / 4);
    dst[threadIdx.x] = src[threadIdx.x];
}

// ---------------- precompute P[t] = Wih[tag_t] @ x_t + bih + bhh ----------------
// grid: (36 tags, 16 row-blocks of 128, 32 chunks of 16 timesteps). block 128.
__global__ void k_precompute(const float* __restrict__ Wih,
                             const float* __restrict__ bih,
                             const float* __restrict__ bhh) {
    __shared__ float4 Xs[16 * 128];   // 16 timesteps x 512 floats = 32 KB
    __shared__ int ts[16];
    int g   = blockIdx.x;
    int cnt = g_tag_cnt[g];
    int c0  = blockIdx.z * 16;
    if (c0 >= cnt) return;            // uniform per CTA
    int m   = min(16, cnt - c0);
    int tid = threadIdx.x;

    if (tid < 16) ts[tid] = (tid < m) ? g_tag_list[g * SEQ + c0 + tid] : 0;
    __syncthreads();

    #pragma unroll
    for (int it = 0; it < 16; ++it) {
        int i = it * 128 + tid;
        int n = i >> 7, kk = i & 127;
        Xs[i] = (n < m) ? ((const float4*)g_embeds)[(size_t)ts[n] * 128 + kk]
                        : make_float4(0.f, 0.f, 0.f, 0.f);
    }
    __syncthreads();

    int r = blockIdx.y * 128 + tid;   // 0..2047
    const float4* wrow = (const float4*)(Wih + ((size_t)g * G4 + r) * EMB);

    float acc[16];
    #pragma unroll
    for (int n = 0; n < 16; ++n) acc[n] = 0.f;

    #pragma unroll 2
    for (int kk = 0; kk < 128; ++kk) {
        float4 w = wrow[kk];
        #pragma unroll
        for (int n = 0; n < 16; ++n) {
            float4 xv = Xs[n * 128 + kk];   // broadcast, conflict-free
            acc[n] += w.x * xv.x + w.y * xv.y + w.z * xv.z + w.w * xv.w;
        }
    }

    float bias = bih[g * G4 + r] + bhh[g * G4 + r];
    for (int n = 0; n < m; ++n)
        g_P[(size_t)ts[n] * G4 + r] = acc[n] + bias;
}

// ---------------- persistent recurrent kernel ----------------
// grid 128 CTAs x 128 threads (4 warps). warp w of CTA b owns j = b*4+w.
__global__ void __launch_bounds__(128, 1) k_seq(const float* __restrict__ Whh,
                                                const int* __restrict__ tags) {
    __shared__ float4 hs4[HID / 4];   // 2 KB staging of h_{t-1}
    int tid  = threadIdx.x;
    int lane = tid & 31;
    int warp = tid >> 5;
    int j    = blockIdx.x * 4 + warp;

    float c = g_c[j];                 // lane 0's value is the live one

    for (int t = 0; t < SEQ; ++t) {
        // stage h_{t-1} into smem
        const float4* hg = (const float4*)g_h[t & 1];
        hs4[tid] = hg[tid];           // 128 threads x float4 = 512 floats
        __syncthreads();

        int tag = tags[t];
        const float4* w = (const float4*)(Whh + ((size_t)tag * G4 + j) * HID);
        const int ROW4 = HID / 4;     // 128 float4 per row

        float di = 0.f, df = 0.f, dg = 0.f, dq = 0.f;
        #pragma unroll
        for (int kk = lane; kk < ROW4; kk += 32) {
            float4 hv = hs4[kk];
            float4 a  = w[kk];                 // row j      (gate i)
            float4 b  = w[kk + 512 * ROW4];    // row j+512  (gate f)
            float4 cc = w[kk + 1024 * ROW4];   // row j+1024 (gate g)
            float4 d  = w[kk + 1536 * ROW4];   // row j+1536 (gate o)
            di += a.x * hv.x + a.y * hv.y + a.z * hv.z + a.w * hv.w;
            df += b.x * hv.x + b.y * hv.y + b.z * hv.z + b.w * hv.w;
            dg += cc.x * hv.x + cc.y * hv.y + cc.z * hv.z + cc.w * hv.w;
            dq += d.x * hv.x + d.y * hv.y + d.z * hv.z + d.w * hv.w;
        }
        #pragma unroll
        for (int off = 16; off; off >>= 1) {
            di += __shfl_down_sync(0xffffffffu, di, off);
            df += __shfl_down_sync(0xffffffffu, df, off);
            dg += __shfl_down_sync(0xffffffffu, dg, off);
            dq += __shfl_down_sync(0xffffffffu, dq, off);
        }

        if (lane == 0) {
            const float* Pt = g_P + (size_t)t * G4;
            float gi = di + Pt[j];
            float gf = df + Pt[j + 512];
            float gg = dg + Pt[j + 1024];
            float go = dq + Pt[j + 1536];
            float iv = sigmoidf_(gi);
            float fv = sigmoidf_(gf);
            float gv = tanhf(gg);
            float ov = sigmoidf_(go);
            c = fv * c + iv * gv;
            g_h[(t & 1) ^ 1][j] = ov * tanhf(c);
        }
        __syncthreads();              // protect hs4 reuse

        // grid-wide barrier (all 128 CTAs co-resident on 148 SMs)
        if (tid == 0) {
            __threadfence();
            atomicAdd(&g_bar, 1u);
            unsigned target = (unsigned)gridDim.x * (unsigned)(t + 1);
            volatile unsigned* vb = &g_bar;
            while (*vb < target) { }
            __threadfence();
        }
        __syncthreads();
    }

    if (lane == 0) g_c[j] = c;
}

// ---------------- final fc + sigmoid + pack outputs ----------------
__global__ void k_final(const float* __restrict__ Wfc, const float* __restrict__ bfc,
                        float* __restrict__ out, int out_size) {
    __shared__ float red[16];
    int tid = threadIdx.x;            // 512 threads
    float hv = g_h[0][tid];           // after step 511, h lives in buffer 0
    float v = hv * Wfc[tid];
    #pragma unroll
    for (int off = 16; off; off >>= 1) v += __shfl_down_sync(0xffffffffu, v, off);
    if ((tid & 31) == 0) red[tid >> 5] = v;
    __syncthreads();
    if (tid < 16) {
        float s = red[tid];
        #pragma unroll
        for (int off = 8; off; off >>= 1) s += __shfl_down_sync(0x0000ffffu, s, off);
        if (tid == 0 && out_size > 0)
            out[0] = sigmoidf_(s + bfc[0]);
    }
    if (1 + tid < out_size)   out[1 + tid]   = hv;
    if (513 + tid < out_size) out[513 + tid] = g_c[tid];
}

// ---------------- launcher ----------------
extern "C" void kernel_launch(void* const* d_in, const int* in_sizes, int n_in,
                              void* d_out, int out_size) {
    const int*   x    = (const int*)d_in[0];
    const int*   tags = (const int*)d_in[1];
    const float* h0   = (const float*)d_in[2];
    const float* c0   = (const float*)d_in[3];
    const float* emb  = (const float*)d_in[4];
    const float* Wih  = (const float*)d_in[5];
    const float* Whh  = (const float*)d_in[6];
    const float* bih  = (const float*)d_in[7];
    const float* bhh  = (const float*)d_in[8];
    const float* Wfc  = (const float*)d_in[9];
    const float* bfc  = (const float*)d_in[10];
    (void)in_sizes; (void)n_in;

    k_init<<<1, 512>>>(h0, c0);
    k_group<<<1, 512>>>(tags);
    k_embed<<<512, 128>>>(x, emb);
    k_precompute<<<dim3(NTAG, 16, 32), 128>>>(Wih, bih, bhh);
    k_seq<<<128, 128>>>(Whh, tags);
    k_final<<<1, 512>>>(Wfc, bfc, (float*)d_out, out_size);
}